// round 1
// baseline (speedup 1.0000x reference)
#include <cuda_runtime.h>

// ============================================================================
// SelfAttention: O = softmax((xWq^T+bq)(xWk^T+bk)^T / sqrt(D)) (xWv^T+bv)
// B=4, S=2048, D=1024, fp32.
//
// Round-1 baseline: fp32 FFMA tiled GEMMs + row softmax.
//   k1..k3: Q/K/V = x @ W^T + b        (8192 x 1024 x 1024 each)
//   k4:     Sc    = Q @ K^T * 1/32     (batched 2048 x 2048 x 1024)
//   k5:     softmax rows of Sc
//   k6:     O     = Sc @ V             (batched 2048 x 1024 x 2048)
// Scratch in a static __device__ array (no allocations, graph-capturable).
// ============================================================================

constexpr long ELEMS_QKV = 4L * 2048 * 1024;   // 8,388,608 per tensor
constexpr long ELEMS_SC  = 4L * 2048 * 2048;   // 16,777,216
constexpr long OFF_Q = 0;
constexpr long OFF_K = ELEMS_QKV;
constexpr long OFF_V = 2 * ELEMS_QKV;
constexpr long OFF_S = 3 * ELEMS_QKV;

__device__ float g_scratch[3 * ELEMS_QKV + ELEMS_SC];   // 160 MB static scratch

#define BM 128
#define BN 128
#define BK 8

// C[M,N] = scale * A[M,K] @ op(B) (+ bias), op(B) = B^T ([N,K]) if TRANS_B else B ([K,N]).
// Any of A/B/C may be null -> use g_scratch + offset. blockIdx.z = batch.
template <bool TRANS_B, bool HAS_BIAS>
__global__ void __launch_bounds__(256)
gemm_tile(const float* __restrict__ A, const float* __restrict__ Bm,
          const float* __restrict__ bias, float* __restrict__ C,
          long aoff, long boff, long coff,
          int M, int N, int K, float scale,
          long sA, long sB, long sC)
{
    const float* Ap = (A  ? A  : (const float*)g_scratch + aoff) + sA * blockIdx.z;
    const float* Bp = (Bm ? Bm : (const float*)g_scratch + boff) + sB * blockIdx.z;
    float*       Cp = (C  ? C  : g_scratch + coff)               + sC * blockIdx.z;

    __shared__ __align__(16) float As[BK][BM];
    __shared__ __align__(16) float Bs[BK][BN];

    const int tid  = threadIdx.x;
    const int tx   = tid & 15;   // 0..15  -> output cols tx*8..tx*8+7
    const int ty   = tid >> 4;   // 0..15  -> output rows ty*8..ty*8+7
    const int row0 = blockIdx.y * BM;
    const int col0 = blockIdx.x * BN;

    // A tile loader: thread -> (row ra, k-offset ka), float4 along K
    const int ra = tid >> 1;          // 0..127
    const int ka = (tid & 1) * 4;     // 0 or 4
    // B tile loader (non-transposed case): row kb, col nb, float4 along N
    const int kb = tid >> 5;          // 0..7
    const int nb = (tid & 31) * 4;    // 0..124

    float acc[8][8];
#pragma unroll
    for (int i = 0; i < 8; i++)
#pragma unroll
        for (int j = 0; j < 8; j++) acc[i][j] = 0.f;

    for (int k0 = 0; k0 < K; k0 += BK) {
        // --- load A tile [BM x BK] into As[k][m] ---
        {
            float4 v = *reinterpret_cast<const float4*>(
                &Ap[(long)(row0 + ra) * K + k0 + ka]);
            As[ka + 0][ra] = v.x;
            As[ka + 1][ra] = v.y;
            As[ka + 2][ra] = v.z;
            As[ka + 3][ra] = v.w;
        }
        // --- load B tile into Bs[k][n] ---
        if (TRANS_B) {
            float4 v = *reinterpret_cast<const float4*>(
                &Bp[(long)(col0 + ra) * K + k0 + ka]);
            Bs[ka + 0][ra] = v.x;
            Bs[ka + 1][ra] = v.y;
            Bs[ka + 2][ra] = v.z;
            Bs[ka + 3][ra] = v.w;
        } else {
            float4 v = *reinterpret_cast<const float4*>(
                &Bp[(long)(k0 + kb) * N + col0 + nb]);
            *reinterpret_cast<float4*>(&Bs[kb][nb]) = v;
        }
        __syncthreads();

#pragma unroll
        for (int kk = 0; kk < BK; kk++) {
            float a[8], b[8];
#pragma unroll
            for (int h = 0; h < 2; h++) {
                float4 ta = *reinterpret_cast<const float4*>(&As[kk][ty * 8 + h * 4]);
                a[h * 4 + 0] = ta.x; a[h * 4 + 1] = ta.y;
                a[h * 4 + 2] = ta.z; a[h * 4 + 3] = ta.w;
                float4 tb = *reinterpret_cast<const float4*>(&Bs[kk][tx * 8 + h * 4]);
                b[h * 4 + 0] = tb.x; b[h * 4 + 1] = tb.y;
                b[h * 4 + 2] = tb.z; b[h * 4 + 3] = tb.w;
            }
#pragma unroll
            for (int i = 0; i < 8; i++)
#pragma unroll
                for (int j = 0; j < 8; j++)
                    acc[i][j] = fmaf(a[i], b[j], acc[i][j]);
        }
        __syncthreads();
    }

    // --- epilogue: scale (+bias), vectorized store ---
#pragma unroll
    for (int i = 0; i < 8; i++) {
        const long r = row0 + ty * 8 + i;
#pragma unroll
        for (int j = 0; j < 8; j += 4) {
            const int c = col0 + tx * 8 + j;
            float4 v;
            v.x = acc[i][j + 0] * scale;
            v.y = acc[i][j + 1] * scale;
            v.z = acc[i][j + 2] * scale;
            v.w = acc[i][j + 3] * scale;
            if (HAS_BIAS) {
                v.x += bias[c + 0];
                v.y += bias[c + 1];
                v.z += bias[c + 2];
                v.w += bias[c + 3];
            }
            *reinterpret_cast<float4*>(&Cp[r * N + c]) = v;
        }
    }
}

// In-place row softmax over rows of length n (n = 2048, 8 elems/thread cached
// in registers: single global read + single global write per element).
__global__ void __launch_bounds__(256)
softmax_rows(long off, int n)
{
    float* p = g_scratch + off + (long)blockIdx.x * n;
    __shared__ float red[256];
    const int t = threadIdx.x;
    const int per = n >> 8;   // 8 for n=2048

    float v[8];
    float m = -3.4e38f;
#pragma unroll
    for (int i = 0; i < 8; i++) {
        if (i < per) {
            v[i] = p[t + (i << 8)];
            m = fmaxf(m, v[i]);
        }
    }
    red[t] = m;
    __syncthreads();
    for (int s = 128; s > 0; s >>= 1) {
        if (t < s) red[t] = fmaxf(red[t], red[t + s]);
        __syncthreads();
    }
    m = red[0];
    __syncthreads();

    float sum = 0.f;
#pragma unroll
    for (int i = 0; i < 8; i++) {
        if (i < per) {
            v[i] = __expf(v[i] - m);
            sum += v[i];
        }
    }
    red[t] = sum;
    __syncthreads();
    for (int s = 128; s > 0; s >>= 1) {
        if (t < s) red[t] += red[t + s];
        __syncthreads();
    }
    const float inv = 1.f / red[0];

#pragma unroll
    for (int i = 0; i < 8; i++)
        if (i < per) p[t + (i << 8)] = v[i] * inv;
}

extern "C" void kernel_launch(void* const* d_in, const int* in_sizes, int n_in,
                              void* d_out, int out_size)
{
    const float* x  = (const float*)d_in[0];
    const float* Wq = (const float*)d_in[1];
    const float* bq = (const float*)d_in[2];
    const float* Wk = (const float*)d_in[3];
    const float* bk = (const float*)d_in[4];
    const float* Wv = (const float*)d_in[5];
    const float* bv = (const float*)d_in[6];
    float* out = (float*)d_out;

    const int B = 4, S = 2048, D = 1024;
    const long SD = (long)S * D;   // per-batch Q/K/V/O stride
    const long SS = (long)S * S;   // per-batch score stride
    dim3 thr(256);

    // Q/K/V = x @ W^T + b   (M=B*S=8192, N=D, K=D)
    dim3 g_qkv(D / BN, (B * S) / BM, 1);
    gemm_tile<true, true><<<g_qkv, thr>>>(x, Wq, bq, nullptr, 0, 0, OFF_Q,
                                          B * S, D, D, 1.f, 0, 0, 0);
    gemm_tile<true, true><<<g_qkv, thr>>>(x, Wk, bk, nullptr, 0, 0, OFF_K,
                                          B * S, D, D, 1.f, 0, 0, 0);
    gemm_tile<true, true><<<g_qkv, thr>>>(x, Wv, bv, nullptr, 0, 0, OFF_V,
                                          B * S, D, D, 1.f, 0, 0, 0);

    // Sc = Q @ K^T / sqrt(D)   (batched, M=N=S, K=D)
    dim3 g_sc(S / BN, S / BM, B);
    gemm_tile<true, false><<<g_sc, thr>>>(nullptr, nullptr, nullptr, nullptr,
                                          OFF_Q, OFF_K, OFF_S,
                                          S, S, D, 0.03125f, SD, SD, SS);

    // row softmax over Sc
    softmax_rows<<<B * S, thr>>>(OFF_S, S);

    // O = Sc @ V   (batched, M=S, N=D, K=S; B not transposed)
    dim3 g_o(D / BN, S / BM, B);
    gemm_tile<false, false><<<g_o, thr>>>(nullptr, nullptr, nullptr, out,
                                          OFF_S, OFF_V, 0,
                                          S, D, S, 1.f, SS, SD, SD);
}

// round 3
// speedup vs baseline: 2.5802x; 2.5802x over previous
#include <cuda_runtime.h>
#include <cuda_bf16.h>
#include <cstdint>

// ============================================================================
// SelfAttention via mma.sync (HMMA.16816 bf16) — tcgen05 is PTX-gated to
// sm_103a and this harness compiles PTX at compute_103, so we use the legacy
// tensor-core path which needs no arch-variant suffix.
//
//   k1: Q = x@Wq^T+bq      k2: K = x@Wk^T+bk      k3: VT = (x@Wv^T+bv)^T
//   k4: Sc = Q@K^T /32     k5: softmax rows       k6: O = Sc@VT^T
//
// GEMM CTA: 128x128 tile, 512 thr (16 warps, warp 32x32), K-chunks of 64.
// fp32 LDG prefetch -> bf16 hi/lo split -> SW128 smem -> ldmatrix -> 3 MMAs
// per logical MMA (hi*hi + hi*lo + lo*hi), fp32 accum in registers.
// ============================================================================

constexpr int S = 2048, D = 1024, NB = 4;
constexpr long SD  = (long)S * D;
constexpr long SSZ = (long)S * S;
constexpr long OFF_Q = 0, OFF_K = (long)NB * SD, OFF_VT = 2L * NB * SD,
               OFF_S = 3L * NB * SD;
__device__ float g_scratch[3L * NB * SD + (long)NB * SSZ];   // 160 MB

constexpr int STAGE  = 64 * 1024;                 // Ahi|Alo|Bhi|Blo x 16KB
constexpr int OFF_AH = 0, OFF_AL = 16384, OFF_BH = 32768, OFF_BL = 49152;
constexpr int SMEM_DYN = 2 * STAGE + 1024;

#define SWZ(o) ((o) ^ (((o) >> 3) & 0x70))

// ---------------------------------------------------------------- helpers
__device__ __forceinline__ uint32_t smem_u32(const void* p) {
    uint32_t a;
    asm("{ .reg .u64 t; cvta.to.shared.u64 t, %1; cvt.u32.u64 %0, t; }"
        : "=r"(a) : "l"(p));
    return a;
}
__device__ __forceinline__ void ldsm4(uint32_t* r, uint32_t addr) {
    asm volatile("ldmatrix.sync.aligned.m8n8.x4.shared.b16 {%0,%1,%2,%3}, [%4];"
                 : "=r"(r[0]), "=r"(r[1]), "=r"(r[2]), "=r"(r[3]) : "r"(addr));
}
__device__ __forceinline__ void mma16816(float* d, const uint32_t* a,
                                         const uint32_t* b) {
    asm volatile(
        "mma.sync.aligned.m16n8k16.row.col.f32.bf16.bf16.f32 "
        "{%0,%1,%2,%3}, {%4,%5,%6,%7}, {%8,%9}, {%0,%1,%2,%3};"
        : "+f"(d[0]), "+f"(d[1]), "+f"(d[2]), "+f"(d[3])
        : "r"(a[0]), "r"(a[1]), "r"(a[2]), "r"(a[3]), "r"(b[0]), "r"(b[1]));
}
// bf16 hi/lo split of a float4, 8B each into (swizzled) smem
__device__ __forceinline__ void split_store(char* hi_p, char* lo_p, float4 v) {
    __nv_bfloat16 hx = __float2bfloat16_rn(v.x);
    __nv_bfloat16 hy = __float2bfloat16_rn(v.y);
    __nv_bfloat16 hz = __float2bfloat16_rn(v.z);
    __nv_bfloat16 hw = __float2bfloat16_rn(v.w);
    __nv_bfloat162 h01 = __nv_bfloat162(hx, hy), h23 = __nv_bfloat162(hz, hw);
    __nv_bfloat16 lx = __float2bfloat16_rn(v.x - __bfloat162float(hx));
    __nv_bfloat16 ly = __float2bfloat16_rn(v.y - __bfloat162float(hy));
    __nv_bfloat16 lz = __float2bfloat16_rn(v.z - __bfloat162float(hz));
    __nv_bfloat16 lw = __float2bfloat16_rn(v.w - __bfloat162float(hw));
    __nv_bfloat162 l01 = __nv_bfloat162(lx, ly), l23 = __nv_bfloat162(lz, lw);
    *reinterpret_cast<uint2*>(hi_p) = make_uint2(
        *reinterpret_cast<uint32_t*>(&h01), *reinterpret_cast<uint32_t*>(&h23));
    *reinterpret_cast<uint2*>(lo_p) = make_uint2(
        *reinterpret_cast<uint32_t*>(&l01), *reinterpret_cast<uint32_t*>(&l23));
}

// ---------------------------------------------------------------- GEMM
// C[128x128 tile] = scale * A[M,K](K-major,lda) @ B[N,K](K-major,ldb)^T (+bias)
// trans_out: C[n*ldt + m]  else C[m*ldc + n].
__global__ void __launch_bounds__(512, 1)
mma_gemm(const float* __restrict__ A, const float* __restrict__ Bm,
         const float* __restrict__ bias, float* __restrict__ Cout,
         long aoff, long boff, long coff,
         int K, int lda, int ldb, int ldc, int ldt,
         long sA, long sB, long sC, float scale, int has_bias, int trans_out)
{
    const float* Ap = (A   ? A   : (const float*)g_scratch + aoff) + sA * blockIdx.z;
    const float* Bp = (Bm  ? Bm  : (const float*)g_scratch + boff) + sB * blockIdx.z;
    float*       Cp = (Cout? Cout: g_scratch + coff)               + sC * blockIdx.z;

    extern __shared__ char smem_raw[];
    const uint32_t rawb  = smem_u32(smem_raw);
    const uint32_t abase = (rawb + 1023) & ~1023u;
    char* smem = smem_raw + (abase - rawb);

    const int tid = threadIdx.x, lane = tid & 31, wid = tid >> 5;
    const long row0 = (long)blockIdx.y * 128, col0 = (long)blockIdx.x * 128;

    // ---- loader mapping: 512 thr; c4 = float4 col (0..15), rg = row (0..31)
    const int c4 = tid & 15, rg = tid >> 4;
    const int so_base = SWZ(rg * 128 + c4 * 8);     // rows rg+32j: +j*4096

    // ---- fragment lane constants (warp 32x32 at (mw,nw))
    const int mw = (wid >> 2) * 32, nw = (wid & 3) * 32;
    uint32_t a_row[2], a_swz[2];
#pragma unroll
    for (int i = 0; i < 2; i++) {
        uint32_t rb = (uint32_t)(mw + 16 * i + (lane & 15)) * 128;
        a_row[i] = rb; a_swz[i] = (rb >> 3) & 0x70;
    }
    const uint32_t a_kl = (uint32_t)((lane >> 4) << 4);      // 0 / 16
    uint32_t b_row[2], b_swz[2];
#pragma unroll
    for (int p = 0; p < 2; p++) {
        uint32_t rb = (uint32_t)(nw + 16 * p + (lane & 7) + ((lane & 16) >> 1)) * 128;
        b_row[p] = rb; b_swz[p] = (rb >> 3) & 0x70;
    }
    const uint32_t b_kl = (uint32_t)((lane & 8) << 1);       // 0 / 16

    float acc[32];
#pragma unroll
    for (int i = 0; i < 32; i++) acc[i] = 0.f;

    const int nch = K >> 6;
    float4 pa[4], pb[4];

    // ---- prologue: load + store chunk 0
    {
        const float* ap = Ap + (row0 + rg) * (long)lda + c4 * 4;
        const float* bp = Bp + (col0 + rg) * (long)ldb + c4 * 4;
#pragma unroll
        for (int j = 0; j < 4; j++) {
            pa[j] = *reinterpret_cast<const float4*>(ap + (long)32 * j * lda);
            pb[j] = *reinterpret_cast<const float4*>(bp + (long)32 * j * ldb);
        }
        char* st = smem;
#pragma unroll
        for (int j = 0; j < 4; j++) {
            const int so = so_base + j * 4096;
            split_store(st + OFF_AH + so, st + OFF_AL + so, pa[j]);
            split_store(st + OFF_BH + so, st + OFF_BL + so, pb[j]);
        }
    }
    __syncthreads();

    for (int ch = 0; ch < nch; ch++) {
        if (ch + 1 < nch) {   // prefetch next chunk into registers
            const float* ap = Ap + (row0 + rg) * (long)lda + (long)(ch + 1) * 64 + c4 * 4;
            const float* bp = Bp + (col0 + rg) * (long)ldb + (long)(ch + 1) * 64 + c4 * 4;
#pragma unroll
            for (int j = 0; j < 4; j++) {
                pa[j] = *reinterpret_cast<const float4*>(ap + (long)32 * j * lda);
                pb[j] = *reinterpret_cast<const float4*>(bp + (long)32 * j * ldb);
            }
        }
        const uint32_t sb = abase + (uint32_t)(ch & 1) * STAGE;
#pragma unroll
        for (int ks = 0; ks < 4; ks++) {
            const uint32_t KB = ks * 32;
            uint32_t af[2][4], bh[8], bl[8];
#pragma unroll
            for (int i = 0; i < 2; i++)
                ldsm4(af[i], sb + OFF_AH + a_row[i] + ((KB + a_kl) ^ a_swz[i]));
#pragma unroll
            for (int p = 0; p < 2; p++) {
                const uint32_t ko = (KB + b_kl);
                ldsm4(&bh[4 * p], sb + OFF_BH + b_row[p] + (ko ^ b_swz[p]));
                ldsm4(&bl[4 * p], sb + OFF_BL + b_row[p] + (ko ^ b_swz[p]));
            }
#pragma unroll
            for (int i = 0; i < 2; i++)
#pragma unroll
                for (int j = 0; j < 4; j++) {
                    mma16816(acc + (i * 4 + j) * 4, af[i], &bh[j * 2]);  // hi*hi
                    mma16816(acc + (i * 4 + j) * 4, af[i], &bl[j * 2]);  // hi*lo
                }
#pragma unroll
            for (int i = 0; i < 2; i++)   // reuse af regs for A-lo
                ldsm4(af[i], sb + OFF_AL + a_row[i] + ((KB + a_kl) ^ a_swz[i]));
#pragma unroll
            for (int i = 0; i < 2; i++)
#pragma unroll
                for (int j = 0; j < 4; j++)
                    mma16816(acc + (i * 4 + j) * 4, af[i], &bh[j * 2]);  // lo*hi
        }
        __syncthreads();
        if (ch + 1 < nch) {
            char* st = smem + ((ch + 1) & 1) * STAGE;
#pragma unroll
            for (int j = 0; j < 4; j++) {
                const int so = so_base + j * 4096;
                split_store(st + OFF_AH + so, st + OFF_AL + so, pa[j]);
                split_store(st + OFF_BH + so, st + OFF_BL + so, pb[j]);
            }
            __syncthreads();
        }
    }

    // ---- epilogue: d0,d1 = row qr, cols 2qc,2qc+1; d2,d3 = row qr+8
    const int qr = lane >> 2, qc = lane & 3;
#pragma unroll
    for (int i = 0; i < 2; i++)
#pragma unroll
        for (int j = 0; j < 4; j++) {
            const float* d = acc + (i * 4 + j) * 4;
#pragma unroll
            for (int h = 0; h < 2; h++) {
                const long r = row0 + mw + 16 * i + qr + 8 * h;
                const long c = col0 + nw + 8 * j + 2 * qc;
                float v0 = d[2 * h + 0] * scale, v1 = d[2 * h + 1] * scale;
                if (has_bias) { v0 += bias[c]; v1 += bias[c + 1]; }
                if (trans_out) {
                    Cp[c * (long)ldt + r]       = v0;
                    Cp[(c + 1) * (long)ldt + r] = v1;
                } else {
                    *reinterpret_cast<float2*>(&Cp[r * (long)ldc + c]) =
                        make_float2(v0, v1);
                }
            }
        }
}

// ---------------------------------------------------------------- softmax
__global__ void __launch_bounds__(256)
softmax_rows(long off, int n)
{
    float* p = g_scratch + off + (long)blockIdx.x * n;
    __shared__ float red[256];
    const int t = threadIdx.x;

    float v[8];
    float m = -3.4e38f;
#pragma unroll
    for (int i = 0; i < 8; i++) { v[i] = p[t + (i << 8)]; m = fmaxf(m, v[i]); }
    red[t] = m;
    __syncthreads();
    for (int s = 128; s > 0; s >>= 1) {
        if (t < s) red[t] = fmaxf(red[t], red[t + s]);
        __syncthreads();
    }
    m = red[0];
    __syncthreads();

    float sum = 0.f;
#pragma unroll
    for (int i = 0; i < 8; i++) { v[i] = __expf(v[i] - m); sum += v[i]; }
    red[t] = sum;
    __syncthreads();
    for (int s = 128; s > 0; s >>= 1) {
        if (t < s) red[t] += red[t + s];
        __syncthreads();
    }
    const float inv = 1.f / red[0];
#pragma unroll
    for (int i = 0; i < 8; i++) p[t + (i << 8)] = v[i] * inv;
}

// ---------------------------------------------------------------- launch
extern "C" void kernel_launch(void* const* d_in, const int* in_sizes, int n_in,
                              void* d_out, int out_size)
{
    const float* x  = (const float*)d_in[0];
    const float* Wq = (const float*)d_in[1];
    const float* bq = (const float*)d_in[2];
    const float* Wk = (const float*)d_in[3];
    const float* bk = (const float*)d_in[4];
    const float* Wv = (const float*)d_in[5];
    const float* bv = (const float*)d_in[6];
    float* out = (float*)d_out;

    cudaFuncSetAttribute(mma_gemm, cudaFuncAttributeMaxDynamicSharedMemorySize,
                         SMEM_DYN);
    dim3 thr(512);

    // Q, K: M=8192 (batch folded), N=D, K=D
    dim3 g_qk(D / 128, (NB * S) / 128, 1);
    mma_gemm<<<g_qk, thr, SMEM_DYN>>>(x, Wq, bq, nullptr, 0, 0, OFF_Q,
                                      D, D, D, D, 0, 0, 0, 0, 1.f, 1, 0);
    mma_gemm<<<g_qk, thr, SMEM_DYN>>>(x, Wk, bk, nullptr, 0, 0, OFF_K,
                                      D, D, D, D, 0, 0, 0, 0, 1.f, 1, 0);

    // VT[b][d][s] = (x@Wv^T+bv)^T : transposed epilogue, ldt=S
    dim3 g_v(D / 128, S / 128, NB);
    mma_gemm<<<g_v, thr, SMEM_DYN>>>(x, Wv, bv, nullptr, 0, 0, OFF_VT,
                                     D, D, D, 0, S, SD, 0, SD, 1.f, 1, 1);

    // Sc = Q@K^T / 32 : batched
    dim3 g_sc(S / 128, S / 128, NB);
    mma_gemm<<<g_sc, thr, SMEM_DYN>>>(nullptr, nullptr, nullptr, nullptr,
                                      OFF_Q, OFF_K, OFF_S,
                                      D, D, D, S, 0, SD, SD, SSZ,
                                      0.03125f, 0, 0);

    softmax_rows<<<NB * S, 256>>>(OFF_S, S);

    // O = Sc @ VT^T : batched, K=S
    dim3 g_o(D / 128, S / 128, NB);
    mma_gemm<<<g_o, thr, SMEM_DYN>>>(nullptr, nullptr, nullptr, out,
                                     OFF_S, OFF_VT, 0,
                                     S, S, S, D, 0, SSZ, SD, SD,
                                     1.f, 0, 0);
}

// round 4
// speedup vs baseline: 3.1758x; 1.2308x over previous
#include <cuda_runtime.h>
#include <cuda_bf16.h>
#include <cstdint>

// ============================================================================
// SelfAttention, mma.sync bf16x3-split, cp.async 3-stage pipelined GEMMs.
// All operands pre-split to bf16 hi/lo in GMEM (by tiny split kernels or by
// producer epilogues), so the GEMM mainloop is pure cp.async+ldmatrix+HMMA.
//   s1..s4: split x, Wq, Wk, Wv -> bf16 hi/lo
//   k1: Qh/l = x@Wq^T+bq     k2: Kh/l = x@Wk^T+bk   k3: VTh/l = (x@Wv^T+bv)^T
//   k4: Sc(f32) = Q@K^T/32   k5: softmax -> Ph/l    k6: O = P@VT^T -> out
// ============================================================================

constexpr int S = 2048, D = 1024, NB = 4;
constexpr long SD  = (long)S * D;
constexpr long SSZ = (long)S * S;
constexpr long NX = (long)NB * S * D;      // 8,388,608
constexpr long NW = (long)D * D;           // 1,048,576
constexpr long NP = (long)NB * S * S;      // 16,777,216

// bf16 scratch offsets (elements)
constexpr long OXH = 0,        OXL = NX;
constexpr long OWQH = 2*NX,    OWQL = OWQH+NW, OWKH = OWQH+2*NW, OWKL = OWQH+3*NW,
               OWVH = OWQH+4*NW, OWVL = OWQH+5*NW;
constexpr long OQH = 2*NX+6*NW, OQL = OQH+NX, OKH = OQH+2*NX, OKL = OQH+3*NX,
               OVTH = OQH+4*NX, OVTL = OQH+5*NX;
constexpr long OPH = OQH+6*NX,  OPL = OPH+NP;
constexpr long NBF = OPL + NP;             // ~107M elems (214 MB)

__device__ __align__(128) __nv_bfloat16 g_bf[NBF];
__device__ float g_sc[NP];                 // fp32 scores (64 MB)

constexpr int STAGE  = 64 * 1024;          // AH|AL|BH|BL x 16KB (128 x 128B)
constexpr int OFF_AH = 0, OFF_AL = 16384, OFF_BH = 32768, OFF_BL = 49152;
constexpr int NSTG   = 3;
constexpr int SMEM_DYN = NSTG * STAGE + 1024;

#define SWZ(o) ((o) ^ (((o) >> 3) & 0x70))

// ---------------------------------------------------------------- helpers
__device__ __forceinline__ uint32_t smem_u32(const void* p) {
    uint32_t a;
    asm("{ .reg .u64 t; cvta.to.shared.u64 t, %1; cvt.u32.u64 %0, t; }"
        : "=r"(a) : "l"(p));
    return a;
}
__device__ __forceinline__ void ldsm4(uint32_t* r, uint32_t addr) {
    asm volatile("ldmatrix.sync.aligned.m8n8.x4.shared.b16 {%0,%1,%2,%3}, [%4];"
                 : "=r"(r[0]), "=r"(r[1]), "=r"(r[2]), "=r"(r[3]) : "r"(addr));
}
__device__ __forceinline__ void mma16816(float* d, const uint32_t* a,
                                         const uint32_t* b) {
    asm volatile(
        "mma.sync.aligned.m16n8k16.row.col.f32.bf16.bf16.f32 "
        "{%0,%1,%2,%3}, {%4,%5,%6,%7}, {%8,%9}, {%0,%1,%2,%3};"
        : "+f"(d[0]), "+f"(d[1]), "+f"(d[2]), "+f"(d[3])
        : "r"(a[0]), "r"(a[1]), "r"(a[2]), "r"(a[3]), "r"(b[0]), "r"(b[1]));
}
#define CPA16(dst, src) \
    asm volatile("cp.async.cg.shared.global [%0], [%1], 16;" \
                 :: "r"(dst), "l"(src) : "memory")
#define CP_COMMIT() asm volatile("cp.async.commit_group;" ::: "memory")

__device__ __forceinline__ void split2(float v0, float v1,
                                       uint32_t& h, uint32_t& l) {
    __nv_bfloat16 h0 = __float2bfloat16_rn(v0), h1 = __float2bfloat16_rn(v1);
    __nv_bfloat162 hh(h0, h1);
    __nv_bfloat162 ll(__float2bfloat16_rn(v0 - __bfloat162float(h0)),
                      __float2bfloat16_rn(v1 - __bfloat162float(h1)));
    h = *reinterpret_cast<uint32_t*>(&hh);
    l = *reinterpret_cast<uint32_t*>(&ll);
}

// ---------------------------------------------------------------- split kernel
__global__ void __launch_bounds__(256)
split_arr(const float* __restrict__ in, __nv_bfloat16* __restrict__ oh,
          __nv_bfloat16* __restrict__ ol, long n)
{
    long i = ((long)blockIdx.x * 256 + threadIdx.x) * 4;
    if (i >= n) return;
    float4 v = *reinterpret_cast<const float4*>(in + i);
    uint2 h, l;
    split2(v.x, v.y, h.x, l.x);
    split2(v.z, v.w, h.y, l.y);
    *reinterpret_cast<uint2*>(oh + i) = h;
    *reinterpret_cast<uint2*>(ol + i) = l;
}

// ---------------------------------------------------------------- GEMM
// C(128x128 tile) = scale * A[M,K](hi/lo bf16, K-major, lda)
//                         @ B[N,K](hi/lo bf16, K-major, ldb)^T (+bias[n])
// mode 0: fp32 out Cf[r*ldc+c]; mode 1: bf16 pair Ch/Cl[r*ldc+c];
// mode 2: bf16 pair transposed Ch/Cl[c*ldc+r].
__global__ void __launch_bounds__(512, 1)
mma_gemm(const __nv_bfloat16* __restrict__ Ah, const __nv_bfloat16* __restrict__ Al,
         const __nv_bfloat16* __restrict__ Bh, const __nv_bfloat16* __restrict__ Bl,
         const float* __restrict__ bias, float* __restrict__ Cf,
         __nv_bfloat16* __restrict__ Ch, __nv_bfloat16* __restrict__ Cl,
         int K, int lda, int ldb, int ldc,
         long sA, long sB, long sC, float scale, int has_bias, int mode)
{
    const long zb = blockIdx.z;
    Ah += sA * zb; Al += sA * zb; Bh += sB * zb; Bl += sB * zb;

    extern __shared__ char smem_raw[];
    const uint32_t rawb  = smem_u32(smem_raw);
    const uint32_t abase = (rawb + 1023) & ~1023u;

    const int tid = threadIdx.x, lane = tid & 31, wid = tid >> 5;
    const long row0 = (long)blockIdx.y * 128, col0 = (long)blockIdx.x * 128;

    // ---- cp.async loader mapping: r0 = row (0..63) [+64], s0 = 16B seg (0..7)
    const int r0 = tid >> 3, s0 = tid & 7;
    const uint32_t w0 = SWZ((uint32_t)r0 * 128 + s0 * 16);
    const uint32_t w1 = SWZ((uint32_t)(r0 + 64) * 128 + s0 * 16);
    const __nv_bfloat16* ga[8] = {
        Ah + (row0 + r0) * (long)lda + s0 * 8,
        Ah + (row0 + r0 + 64) * (long)lda + s0 * 8,
        Al + (row0 + r0) * (long)lda + s0 * 8,
        Al + (row0 + r0 + 64) * (long)lda + s0 * 8,
        Bh + (col0 + r0) * (long)ldb + s0 * 8,
        Bh + (col0 + r0 + 64) * (long)ldb + s0 * 8,
        Bl + (col0 + r0) * (long)ldb + s0 * 8,
        Bl + (col0 + r0 + 64) * (long)ldb + s0 * 8 };
    const uint32_t soff[8] = { OFF_AH + w0, OFF_AH + w1, OFF_AL + w0, OFF_AL + w1,
                               OFF_BH + w0, OFF_BH + w1, OFF_BL + w0, OFF_BL + w1 };

    // ---- fragment lane constants (warp 32x32 at (mw,nw))
    const int mw = (wid >> 2) * 32, nw = (wid & 3) * 32;
    uint32_t a_row[2], a_swz[2];
#pragma unroll
    for (int i = 0; i < 2; i++) {
        uint32_t rb = (uint32_t)(mw + 16 * i + (lane & 15)) * 128;
        a_row[i] = rb; a_swz[i] = (rb >> 3) & 0x70;
    }
    const uint32_t a_kl = (uint32_t)((lane >> 4) << 4);
    uint32_t b_row[2], b_swz[2];
#pragma unroll
    for (int p = 0; p < 2; p++) {
        uint32_t rb = (uint32_t)(nw + 16 * p + (lane & 7) + ((lane & 16) >> 1)) * 128;
        b_row[p] = rb; b_swz[p] = (rb >> 3) & 0x70;
    }
    const uint32_t b_kl = (uint32_t)((lane & 8) << 1);

    float acc[32];
#pragma unroll
    for (int i = 0; i < 32; i++) acc[i] = 0.f;

    const int nch = K >> 6;

    // issue chunk ch into stage ch%3
#define ISSUE(ch) do {                                                        \
        const uint32_t _sb = abase + (uint32_t)((ch) % NSTG) * STAGE;         \
        const long _k = (long)(ch) * 64;                                      \
        _Pragma("unroll")                                                     \
        for (int q = 0; q < 8; q++) CPA16(_sb + soff[q], ga[q] + _k);         \
        CP_COMMIT();                                                          \
    } while (0)

    ISSUE(0);
    ISSUE(1);

    for (int ch = 0; ch < nch; ch++) {
        if (ch + 1 < nch)
            asm volatile("cp.async.wait_group 1;" ::: "memory");
        else
            asm volatile("cp.async.wait_group 0;" ::: "memory");
        __syncthreads();
        if (ch + 2 < nch) ISSUE(ch + 2);

        const uint32_t sb = abase + (uint32_t)(ch % NSTG) * STAGE;
#pragma unroll
        for (int ks = 0; ks < 4; ks++) {
            const uint32_t KB = ks * 32;
            uint32_t af[2][4], bh[8], bl[8];
#pragma unroll
            for (int i = 0; i < 2; i++)
                ldsm4(af[i], sb + OFF_AH + a_row[i] + ((KB + a_kl) ^ a_swz[i]));
#pragma unroll
            for (int p = 0; p < 2; p++) {
                const uint32_t ko = KB + b_kl;
                ldsm4(&bh[4 * p], sb + OFF_BH + b_row[p] + (ko ^ b_swz[p]));
                ldsm4(&bl[4 * p], sb + OFF_BL + b_row[p] + (ko ^ b_swz[p]));
            }
#pragma unroll
            for (int i = 0; i < 2; i++)
#pragma unroll
                for (int j = 0; j < 4; j++) {
                    mma16816(acc + (i * 4 + j) * 4, af[i], &bh[j * 2]);   // hi*hi
                    mma16816(acc + (i * 4 + j) * 4, af[i], &bl[j * 2]);   // hi*lo
                }
#pragma unroll
            for (int i = 0; i < 2; i++)
                ldsm4(af[i], sb + OFF_AL + a_row[i] + ((KB + a_kl) ^ a_swz[i]));
#pragma unroll
            for (int i = 0; i < 2; i++)
#pragma unroll
                for (int j = 0; j < 4; j++)
                    mma16816(acc + (i * 4 + j) * 4, af[i], &bh[j * 2]);   // lo*hi
        }
    }
#undef ISSUE

    // ---- epilogue
    float* Cfp = Cf ? Cf + sC * zb : nullptr;
    __nv_bfloat16* Chp = Ch ? Ch + sC * zb : nullptr;
    __nv_bfloat16* Clp = Cl ? Cl + sC * zb : nullptr;
    const int qr = lane >> 2, qc = lane & 3;
#pragma unroll
    for (int i = 0; i < 2; i++)
#pragma unroll
        for (int j = 0; j < 4; j++) {
            const float* d = acc + (i * 4 + j) * 4;
#pragma unroll
            for (int h = 0; h < 2; h++) {
                const long r = row0 + mw + 16 * i + qr + 8 * h;
                const long c = col0 + nw + 8 * j + 2 * qc;
                float v0 = d[2 * h + 0] * scale, v1 = d[2 * h + 1] * scale;
                if (has_bias) { v0 += bias[c]; v1 += bias[c + 1]; }
                if (mode == 0) {
                    *reinterpret_cast<float2*>(&Cfp[r * (long)ldc + c]) =
                        make_float2(v0, v1);
                } else if (mode == 1) {
                    uint32_t hh, ll;
                    split2(v0, v1, hh, ll);
                    *reinterpret_cast<uint32_t*>(&Chp[r * (long)ldc + c]) = hh;
                    *reinterpret_cast<uint32_t*>(&Clp[r * (long)ldc + c]) = ll;
                } else {
                    __nv_bfloat16 h0 = __float2bfloat16_rn(v0);
                    __nv_bfloat16 h1 = __float2bfloat16_rn(v1);
                    Chp[c * (long)ldc + r]       = h0;
                    Chp[(c + 1) * (long)ldc + r] = h1;
                    Clp[c * (long)ldc + r] =
                        __float2bfloat16_rn(v0 - __bfloat162float(h0));
                    Clp[(c + 1) * (long)ldc + r] =
                        __float2bfloat16_rn(v1 - __bfloat162float(h1));
                }
            }
        }
}

// ---------------------------------------------------------------- softmax
__global__ void __launch_bounds__(256)
softmax_rows(const float* __restrict__ sc, __nv_bfloat16* __restrict__ ph,
             __nv_bfloat16* __restrict__ pl)
{
    const long ro = (long)blockIdx.x * 2048;
    const float* p = sc + ro;
    __shared__ float red[256];
    const int t = threadIdx.x;

    float v[8];
    float m = -3.4e38f;
#pragma unroll
    for (int i = 0; i < 8; i++) { v[i] = p[t + (i << 8)]; m = fmaxf(m, v[i]); }
    red[t] = m;
    __syncthreads();
    for (int s = 128; s > 0; s >>= 1) {
        if (t < s) red[t] = fmaxf(red[t], red[t + s]);
        __syncthreads();
    }
    m = red[0];
    __syncthreads();

    float sum = 0.f;
#pragma unroll
    for (int i = 0; i < 8; i++) { v[i] = __expf(v[i] - m); sum += v[i]; }
    red[t] = sum;
    __syncthreads();
    for (int s = 128; s > 0; s >>= 1) {
        if (t < s) red[t] += red[t + s];
        __syncthreads();
    }
    const float inv = 1.f / red[0];
#pragma unroll
    for (int i = 0; i < 8; i++) {
        float pv = v[i] * inv;
        __nv_bfloat16 h = __float2bfloat16_rn(pv);
        ph[ro + t + (i << 8)] = h;
        pl[ro + t + (i << 8)] = __float2bfloat16_rn(pv - __bfloat162float(h));
    }
}

// ---------------------------------------------------------------- launch
extern "C" void kernel_launch(void* const* d_in, const int* in_sizes, int n_in,
                              void* d_out, int out_size)
{
    const float* x  = (const float*)d_in[0];
    const float* Wq = (const float*)d_in[1];
    const float* bq = (const float*)d_in[2];
    const float* Wk = (const float*)d_in[3];
    const float* bk = (const float*)d_in[4];
    const float* Wv = (const float*)d_in[5];
    const float* bv = (const float*)d_in[6];
    float* out = (float*)d_out;

    __nv_bfloat16* bf; float* scp;
    cudaGetSymbolAddress((void**)&bf, g_bf);
    cudaGetSymbolAddress((void**)&scp, g_sc);

    cudaFuncSetAttribute(mma_gemm, cudaFuncAttributeMaxDynamicSharedMemorySize,
                         SMEM_DYN);
    dim3 thr(512);

    // splits: x, Wq, Wk, Wv -> bf16 hi/lo
    split_arr<<<(int)(NX / 1024), 256>>>(x,  bf + OXH,  bf + OXL,  NX);
    split_arr<<<(int)(NW / 1024), 256>>>(Wq, bf + OWQH, bf + OWQL, NW);
    split_arr<<<(int)(NW / 1024), 256>>>(Wk, bf + OWKH, bf + OWKL, NW);
    split_arr<<<(int)(NW / 1024), 256>>>(Wv, bf + OWVH, bf + OWVL, NW);

    // Q, K: M=8192 (batch folded), N=D, K=D -> bf16 pair (mode 1)
    dim3 g_qk(D / 128, (NB * S) / 128, 1);
    mma_gemm<<<g_qk, thr, SMEM_DYN>>>(bf+OXH, bf+OXL, bf+OWQH, bf+OWQL, bq,
                                      nullptr, bf+OQH, bf+OQL,
                                      D, D, D, D, 0, 0, 0, 1.f, 1, 1);
    mma_gemm<<<g_qk, thr, SMEM_DYN>>>(bf+OXH, bf+OXL, bf+OWKH, bf+OWKL, bk,
                                      nullptr, bf+OKH, bf+OKL,
                                      D, D, D, D, 0, 0, 0, 1.f, 1, 1);

    // VT[b][d][s]: per-batch transposed epilogue (mode 2, ldc = S)
    dim3 g_v(D / 128, S / 128, NB);
    mma_gemm<<<g_v, thr, SMEM_DYN>>>(bf+OXH, bf+OXL, bf+OWVH, bf+OWVL, bv,
                                     nullptr, bf+OVTH, bf+OVTL,
                                     D, D, D, S, SD, 0, SD, 1.f, 1, 2);

    // Sc = Q@K^T / 32 (fp32 out, mode 0), batched
    dim3 g_sc(S / 128, S / 128, NB);
    mma_gemm<<<g_sc, thr, SMEM_DYN>>>(bf+OQH, bf+OQL, bf+OKH, bf+OKL, nullptr,
                                      scp, nullptr, nullptr,
                                      D, D, D, S, SD, SD, SSZ, 0.03125f, 0, 0);

    // softmax -> P hi/lo bf16
    softmax_rows<<<NB * S, 256>>>(scp, bf + OPH, bf + OPL);

    // O = P@VT^T (fp32 out), batched, K = S
    dim3 g_o(D / 128, S / 128, NB);
    mma_gemm<<<g_o, thr, SMEM_DYN>>>(bf+OPH, bf+OPL, bf+OVTH, bf+OVTL, nullptr,
                                     out, nullptr, nullptr,
                                     S, S, S, D, SSZ, SD, SD, 1.f, 0, 0);
}